// round 2
// baseline (speedup 1.0000x reference)
#include <cuda_runtime.h>
#include <cuda_bf16.h>

// Problem: Gridding — trilinear scatter of B=64 x N=65536 points into 64^3 grids.
// ptcloud: (64, 65536, 3) float32 in [-1,1); output (64, 262144) float32.

#define GB 64          // batch
#define GN 65536       // points per batch
#define GS 64          // grid size per dim
#define GRID_CELLS (GS * GS * GS)   // 262144
#define TOTAL_PTS  (GB * GN)        // 4194304
#define OUT_ELEMS  (GB * GRID_CELLS)

__global__ void zero_out_kernel(float4* __restrict__ out) {
    int i = blockIdx.x * blockDim.x + threadIdx.x;
    // OUT_ELEMS/4 = 4194304 float4s
    if (i < OUT_ELEMS / 4) out[i] = make_float4(0.f, 0.f, 0.f, 0.f);
}

__global__ void gridding_scatter_kernel(const float* __restrict__ pt,
                                        float* __restrict__ grid) {
    int gid = blockIdx.x * blockDim.x + threadIdx.x;
    if (gid >= TOTAL_PTS) return;

    int b = gid >> 16;  // gid / GN

    const float* p3 = pt + (size_t)gid * 3;
    float px = p3[0] * 32.0f;
    float py = p3[1] * 32.0f;
    float pz = p3[2] * 32.0f;

    // nz_mask: sum(|p|) != 0
    if (fabsf(px) + fabsf(py) + fabsf(pz) == 0.0f) return;

    float lx = floorf(px), ly = floorf(py), lz = floorf(pz);
    float fx = px - lx, fy = py - ly, fz = pz - lz;

    int ix = (int)lx + 32;
    int iy = (int)ly + 32;
    int iz = (int)lz + 32;

    float wx0 = 1.0f - fx, wx1 = fx;
    float wy0 = 1.0f - fy, wy1 = fy;
    float wz0 = 1.0f - fz, wz1 = fz;

    float* g = grid + (size_t)b * GRID_CELLS;

    #pragma unroll
    for (int i = 0; i < 2; i++) {
        int X = ix + i;
        if ((unsigned)X >= GS) continue;
        float wxv = i ? wx1 : wx0;
        #pragma unroll
        for (int j = 0; j < 2; j++) {
            int Y = iy + j;
            if ((unsigned)Y >= GS) continue;
            float wxy = wxv * (j ? wy1 : wy0);
            int baseXY = (X * GS + Y) * GS;
            #pragma unroll
            for (int k = 0; k < 2; k++) {
                int Z = iz + k;
                if ((unsigned)Z >= GS) continue;
                float w = wxy * (k ? wz1 : wz0);
                atomicAdd(&g[baseXY + Z], w);
            }
        }
    }
}

extern "C" void kernel_launch(void* const* d_in, const int* in_sizes, int n_in,
                              void* d_out, int out_size) {
    const float* pt = (const float*)d_in[0];
    float* out = (float*)d_out;

    // Zero the output grid (d_out is poisoned before timing).
    {
        int n4 = OUT_ELEMS / 4;
        int threads = 256;
        int blocks = (n4 + threads - 1) / threads;
        zero_out_kernel<<<blocks, threads>>>((float4*)out);
    }

    // Scatter trilinear weights.
    {
        int threads = 256;
        int blocks = (TOTAL_PTS + threads - 1) / threads;
        gridding_scatter_kernel<<<blocks, threads>>>(pt, out);
    }
}